// round 14
// baseline (speedup 1.0000x reference)
#include <cuda_runtime.h>

// Problem constants (fixed by setup_inputs):
// B=16, C=1, H=W=128, WS=8, N = B*WS*WS = 1024 windows, mask all ones.
// Canvas per batch: 1024 x 1024. Output = [canvas (16.7M f32) | windows copy (16.7M f32)].

#define NW        1024
#define BATCH     16
#define WSZ       8
#define CELLS     (WSZ * WSZ)        // 64
#define NTILES    (BATCH * CELLS)    // 1024
#define HH        128
#define TILE_F4   (HH * HH / 4)      // 4096 float4 per tile
#define CANV_ROW4 (1024 / 4)
#define CANV_B4   (1024 * 1024 / 4)

#define NSEG      4
#define SEG_F4    (TILE_F4 / NSEG)   // 1024 float4 per segment
#define GTHREADS  256
#define JPT       (SEG_F4 / GTHREADS)// 4 float4 per thread

#define NITEMS    (NTILES * NSEG)    // 4096 work items
#define GRID      740                // 5 CTAs x 148 SMs: one resident wave
#define FETCHES   (NITEMS + GRID)    // 4836: exact fetches consumed per launch

// Monotonic work counter. Every launch consumes EXACTLY FETCHES increments
// (4096 valid items + one terminator per CTA), so item = ctr % FETCHES is
// launch-invariant by induction from 0 -- no reset needed, graph-replay safe.
__device__ unsigned long long g_ctr;

// ---------------------------------------------------------------------------
// Persistent work-stealing kernel, 740 CTAs x 256 threads.
//  1. Each CTA builds the complete window->tile CSR in smem ONCE:
//     mask row sums + shfl scan -> batch csum; classify all 1024 windows
//     (searchsorted-right over csum); counts -> block exclusive scan ->
//     offsets; scatter ids. ~1 L2 round trip + ALU, amortized over ~5.5 items.
//  2. Items (tile,seg), seg fastest, claimed via global atomic counter:
//     near-perfect load balance across the k distribution, no CTA churn,
//     no launch-wave tails. Per item: zero prologue, 2 cheap barriers.
//  3. Data phase per item (proven best config): gather k windows over the
//     1024-float4 segment, 4 independent __ldcs loads in flight per thread,
//     fused verbatim windows copy (each window byte read exactly once
//     chip-wide), then normalized canvas segment (write-back stores).
// ---------------------------------------------------------------------------
__global__ void __launch_bounds__(GTHREADS, 5) hre_persistent_kernel(
    const float4* __restrict__ win4,      // windows as float4
    const int4*   __restrict__ pos4,      // positions as int4 (2 windows each)
    const int4*   __restrict__ mask4,     // mask as int4
    float4* __restrict__ canvas4,         // output canvas (first half)
    float4* __restrict__ copy4)           // output windows copy (second half)
{
    const int tid  = threadIdx.x;
    const int lane = tid & 31;
    const int wid  = tid >> 5;

    __shared__ int csum_s[BATCH];
    __shared__ int cnt[NTILES];           // counts -> cursors -> end pointers
    __shared__ int off[NTILES];           // exclusive offsets (start pointers)
    __shared__ unsigned short ids[NW];    // CSR window ids
    __shared__ int wsum[8], wexcl[8];
    __shared__ int cur_item;

    // --- positions for my 4 windows (issued early, independent) ------------
    const int4 pA = pos4[2 * tid + 0];    // windows 4t+0, 4t+1
    const int4 pB = pos4[2 * tid + 1];    // windows 4t+2, 4t+3

    // --- warp 0: per-batch mask sums + shfl inclusive scan -> csum ----------
    if (tid < 32) {
        int s = 0;
        if (lane < BATCH) {
            #pragma unroll
            for (int j = 0; j < CELLS / 4; ++j) {
                const int4 m = mask4[lane * (CELLS / 4) + j];
                s += m.x + m.y + m.z + m.w;
            }
        }
        #pragma unroll
        for (int o = 1; o < BATCH; o <<= 1) {
            const int n = __shfl_up_sync(0xffffffffu, s, o);
            if (lane >= o) s += n;
        }
        if (lane < BATCH) csum_s[lane] = s;
    }
    // --- all threads: zero counts ------------------------------------------
    #pragma unroll
    for (int j = 0; j < 4; ++j) cnt[tid * 4 + j] = 0;
    __syncthreads();

    // --- classify my 4 windows, count --------------------------------------
    int py[4], px[4], myt[4];
    py[0] = pA.x; px[0] = pA.y;  py[1] = pA.z; px[1] = pA.w;
    py[2] = pB.x; px[2] = pB.y;  py[3] = pB.z; px[3] = pB.w;
    #pragma unroll
    for (int j = 0; j < 4; ++j) {
        const int i = 4 * tid + j;
        int bb = 0;                                       // searchsorted right
        while (bb < BATCH - 1 && i >= csum_s[bb]) ++bb;
        myt[j] = (bb * WSZ + py[j]) * WSZ + px[j];
        atomicAdd(&cnt[myt[j]], 1);
    }
    __syncthreads();

    // --- block exclusive scan over 1024 counts -> offsets -------------------
    int c[4];
    #pragma unroll
    for (int j = 0; j < 4; ++j) c[j] = cnt[4 * tid + j];
    const int s4 = c[0] + c[1] + c[2] + c[3];
    int incl = s4;
    #pragma unroll
    for (int o = 1; o < 32; o <<= 1) {
        const int n = __shfl_up_sync(0xffffffffu, incl, o);
        if (lane >= o) incl += n;
    }
    if (lane == 31) wsum[wid] = incl;
    __syncthreads();
    if (tid == 0) {
        int r = 0;
        #pragma unroll
        for (int w = 0; w < 8; ++w) { wexcl[w] = r; r += wsum[w]; }
    }
    __syncthreads();
    {
        int base = wexcl[wid] + (incl - s4);
        #pragma unroll
        for (int j = 0; j < 4; ++j) {
            off[4 * tid + j] = base;      // exclusive offset
            cnt[4 * tid + j] = base;      // cursor for scatter
            base += c[j];
        }
    }
    __syncthreads();

    // --- scatter window ids into CSR ----------------------------------------
    #pragma unroll
    for (int j = 0; j < 4; ++j) {
        const int slot = atomicAdd(&cnt[myt[j]], 1);
        ids[slot] = (unsigned short)(4 * tid + j);
    }
    // after scatter: off[t] = start, cnt[t] = end
    // (sync happens at top of the work loop)

    // --- persistent work loop ----------------------------------------------
    for (;;) {
        __syncthreads();                  // protects cur_item reuse (and CSR on 1st iter)
        if (tid == 0)
            cur_item = (int)(atomicAdd(&g_ctr, 1ULL) %
                             (unsigned long long)FETCHES);
        __syncthreads();
        const int item = cur_item;
        if (item >= NITEMS) break;        // exactly one terminator per CTA

        const int tile  = item >> 2;      // seg fastest -> tile-local sweeps
        const int seg   = item & 3;
        const int start = off[tile];
        const int end   = cnt[tile];
        const int k     = end - start;

        const int p0 = seg * SEG_F4 + tid;

        float4 acc[JPT];
        #pragma unroll
        for (int j = 0; j < JPT; ++j)
            acc[j] = make_float4(0.f, 0.f, 0.f, 0.f);

        for (int w = start; w < end; ++w) {
            const int wi = ids[w];
            const float4* __restrict__ src = win4  + (size_t)wi * TILE_F4 + p0;
            float4*       __restrict__ dst = copy4 + (size_t)wi * TILE_F4 + p0;

            float4 v[JPT];
            #pragma unroll
            for (int j = 0; j < JPT; ++j)     // 4 independent streaming loads
                v[j] = __ldcs(src + j * GTHREADS);
            #pragma unroll
            for (int j = 0; j < JPT; ++j) {
                dst[j * GTHREADS] = v[j];     // fused windows passthrough
                acc[j].x += v[j].x; acc[j].y += v[j].y;
                acc[j].z += v[j].z; acc[j].w += v[j].w;
            }
        }

        const int b    = tile >> 6;
        const int cell = tile & 63;
        const int ty   = cell >> 3;
        const int tx   = cell & 7;
        const float inv = 1.0f / ((float)k + 1e-6f);
        const int cbase = b * CANV_B4 + ty * HH * CANV_ROW4 + tx * (HH / 4);

        #pragma unroll
        for (int j = 0; j < JPT; ++j) {
            const int p4 = p0 + j * GTHREADS;
            const int r  = p4 >> 5;
            const int c4 = p4 & 31;
            canvas4[cbase + r * CANV_ROW4 + c4] =
                make_float4(acc[j].x * inv, acc[j].y * inv,
                            acc[j].z * inv, acc[j].w * inv);
        }
    }
}

// ---------------------------------------------------------------------------
extern "C" void kernel_launch(void* const* d_in, const int* in_sizes, int n_in,
                              void* d_out, int out_size)
{
    const float* windows   = (const float*)d_in[0];   // [NW,1,128,128] f32
    const int*   positions = (const int*)  d_in[1];   // [NW,2] i32
    const int*   mask      = (const int*)  d_in[2];   // [16,64] i32
    (void)in_sizes; (void)n_in; (void)out_size;

    float* out = (float*)d_out;
    float4* canvas4 = (float4*)out;
    float4* copy4   = (float4*)(out + (size_t)BATCH * 1024 * 1024);

    hre_persistent_kernel<<<GRID, GTHREADS>>>((const float4*)windows,
                                              (const int4*)positions,
                                              (const int4*)mask,
                                              canvas4, copy4);
}

// round 15
// speedup vs baseline: 1.0922x; 1.0922x over previous
#include <cuda_runtime.h>

// Problem constants (fixed by setup_inputs):
// B=16, C=1, H=W=128, WS=8, N = B*WS*WS = 1024 windows, mask all ones.
// Canvas per batch: 1024 x 1024. Output = [canvas (16.7M f32) | windows copy (16.7M f32)].

#define NW        1024            // number of windows
#define BATCH     16
#define WSZ       8
#define CELLS     (WSZ * WSZ)     // 64 cells per batch
#define NTILES    (BATCH * CELLS) // 1024
#define HH        128
#define TILE_F4   (HH * HH / 4)   // 4096 float4 per tile
#define CANV_ROW4 (1024 / 4)      // 256 float4 per canvas row
#define CANV_B4   (1024 * 1024 / 4)

#define NSEG      4               // segments per tile
#define SEG_F4    (TILE_F4 / NSEG)      // 1024 float4 per segment
#define GTHREADS  128
#define JPT       (SEG_F4 / GTHREADS)   // 8 float4 per thread (MLP=8)

// ---------------------------------------------------------------------------
// Single fused kernel: grid (NSEG, NTILES) x 128 threads, seg-major so the 4
// CTAs of one tile sweep each window / the canvas tile contiguously (the R10
// ordering that measured best). This round's change: JPT 4 -> 8 at 128
// threads/block -- doubles per-thread outstanding loads (the binding
// constraint per R4/R10 evidence) while keeping the 4096-block fine
// granularity for k-balance. ~73 regs -> 7 CTAs/SM; depth/SM rises ~1.7x.
//
// Batch-local binning prologue (R10-proven): tile fixes batch b = tile>>6;
// mask row sums via 128 threads x 8 entries + tiny serial csum; scan the
// <=64-window range [csum[b-1], csum[b]) for position matches.
//
// Data phase: gather k windows over this block's 1024-float4 segment with 8
// independent streaming loads in flight per thread, fused verbatim windows
// copy (each window byte read exactly once chip-wide), then the normalized
// canvas segment. Loads read-once -> __ldcs; stores default write-back.
// ---------------------------------------------------------------------------
__global__ void __launch_bounds__(GTHREADS, 7) hre_fused_kernel(
    const float4* __restrict__ win4,      // windows as float4
    const int*    __restrict__ positions, // [NW,2] i32
    const int*    __restrict__ mask,      // [BATCH, CELLS] i32
    float4* __restrict__ canvas4,         // output canvas (first half)
    float4* __restrict__ copy4)           // output windows copy (second half)
{
    const int seg  = blockIdx.x;          // seg-major: consecutive bids share a tile
    const int tile = blockIdx.y;
    const int tid  = threadIdx.x;

    const int b    = tile >> 6;           // batch of this tile
    const int cell = tile & 63;
    const int ty   = cell >> 3;
    const int tx   = cell & 7;

    __shared__ int bsum[BATCH];
    __shared__ int list_cnt;
    __shared__ int win_start, win_n;
    __shared__ unsigned short list[CELLS];

    // --- batch sizes: 128 threads x 8 mask entries = 1024 = BATCH*CELLS ----
    if (tid < BATCH) bsum[tid] = 0;
    if (tid == 0) list_cnt = 0;
    __syncthreads();
    {
        // thread t covers mask[t*8 .. t*8+8); all 8 lie in batch t>>3
        int part = 0;
        #pragma unroll
        for (int j = 0; j < 8; ++j) part += mask[tid * 8 + j];
        atomicAdd(&bsum[tid >> 3], part);
    }
    __syncthreads();
    if (tid == 0) {
        int s = 0, st = 0;
        #pragma unroll
        for (int bb = 0; bb < BATCH; ++bb) {
            if (bb == b) st = s;
            s += bsum[bb];
            if (bb == b) { win_start = st; win_n = s - st; }
        }
    }
    __syncthreads();

    // --- scan only this batch's window range (<= 64 windows) ---------------
    for (int i = win_start + tid; i < win_start + win_n; i += GTHREADS) {
        const int py = positions[2 * i + 0];
        const int px = positions[2 * i + 1];
        if (py == ty && px == tx) {
            const int s = atomicAdd(&list_cnt, 1);
            list[s] = (unsigned short)i;
        }
    }
    __syncthreads();
    const int k = list_cnt;

    // --- gather + fused copy ------------------------------------------------
    const int p0 = seg * SEG_F4 + tid;    // first float4 owned by this thread

    float4 acc[JPT];
    #pragma unroll
    for (int j = 0; j < JPT; ++j)
        acc[j] = make_float4(0.f, 0.f, 0.f, 0.f);

    for (int w = 0; w < k; ++w) {
        const int wi = list[w];
        const float4* __restrict__ src = win4  + (size_t)wi * TILE_F4 + p0;
        float4*       __restrict__ dst = copy4 + (size_t)wi * TILE_F4 + p0;

        float4 v[JPT];
        #pragma unroll
        for (int j = 0; j < JPT; ++j)     // 8 independent streaming loads
            v[j] = __ldcs(src + j * GTHREADS);
        #pragma unroll
        for (int j = 0; j < JPT; ++j) {
            dst[j * GTHREADS] = v[j];     // fused windows passthrough (write-back)
            acc[j].x += v[j].x; acc[j].y += v[j].y;
            acc[j].z += v[j].z; acc[j].w += v[j].w;
        }
    }

    // --- normalized canvas writes ------------------------------------------
    const float inv = 1.0f / ((float)k + 1e-6f);
    const int cbase = b * CANV_B4 + ty * HH * CANV_ROW4 + tx * (HH / 4);

    #pragma unroll
    for (int j = 0; j < JPT; ++j) {
        const int p4 = p0 + j * GTHREADS;       // 0..4095 within tile
        const int r  = p4 >> 5;                 // 32 f4 per tile row
        const int c4 = p4 & 31;
        canvas4[cbase + r * CANV_ROW4 + c4] =
            make_float4(acc[j].x * inv, acc[j].y * inv,
                        acc[j].z * inv, acc[j].w * inv);
    }
}

// ---------------------------------------------------------------------------
extern "C" void kernel_launch(void* const* d_in, const int* in_sizes, int n_in,
                              void* d_out, int out_size)
{
    const float* windows   = (const float*)d_in[0];   // [NW,1,128,128] f32
    const int*   positions = (const int*)  d_in[1];   // [NW,2] i32
    const int*   mask      = (const int*)  d_in[2];   // [16,64] i32
    (void)in_sizes; (void)n_in; (void)out_size;

    float* out = (float*)d_out;
    float4* canvas4 = (float4*)out;
    float4* copy4   = (float4*)(out + (size_t)BATCH * 1024 * 1024);

    dim3 grid(NSEG, NTILES);              // seg-major
    hre_fused_kernel<<<grid, GTHREADS>>>((const float4*)windows, positions, mask,
                                         canvas4, copy4);
}